// round 7
// baseline (speedup 1.0000x reference)
#include <cuda_runtime.h>
#include <cstdint>

#define BH    8
#define DK    64
#define DVV   64
#define NSEQ  2048
#define MF    128
#define CHUNK 128
#define NC    16
#define VP    72          // DV padded: col 64 = ones (z / norm), 65..71 = 0

#define PHI_SCALE 0.08838834764831845f   // 1/sqrt(128)

// Per-(head,chunk) fused chunk state [S | z | pad] : [m][VP], fp32
__device__ float g_S[BH * NC * MF * VP];     // 4.7 MB
__device__ int   g_flag[BH * NC];            // publish flags (reset by kR)

// ---------------------------------------------------------------------------
__device__ __forceinline__ uint32_t f2tf(float f) {
    uint32_t r; asm("cvt.rna.tf32.f32 %0, %1;" : "=r"(r) : "f"(f)); return r;
}
__device__ __forceinline__ void mma8(float* d, const uint32_t* A, const uint32_t* B) {
    asm volatile("mma.sync.aligned.m16n8k8.row.col.f32.tf32.tf32.f32 "
                 "{%0,%1,%2,%3}, {%4,%5,%6,%7}, {%8,%9}, {%0,%1,%2,%3};"
                 : "+f"(d[0]), "+f"(d[1]), "+f"(d[2]), "+f"(d[3])
                 : "r"(A[0]), "r"(A[1]), "r"(A[2]), "r"(A[3]), "r"(B[0]), "r"(B[1]));
}

// Strides (words): A-operand tiles ≡4 (mod 32), B-operand tiles ≡8 (mod 32).
#define STR_KQ  68
#define STR_F   136
#define STR_PKT 136    // phiK^T [m][i] : B in scores (conflict-free), A in state GEMM (2-way)
#define STR_PQ  132    // phiQ  [i][m] : A everywhere
#define STR_SC  132    // Sc    [i][j] : A
#define STR_V   72     // V+    [j][v] : B
#define STR_ST  72     // St+   [m][v] : B

// smem word offsets (regions time-shared by phase)
#define F_    0        // 64 x136 = 8704   (phase 1-2)
#define KQ_   8704     // 128x68  = 8704   (phase 1-2: K, then Q)
#define V_    0        // 128x72  = 9216   (phase 3+)
#define ST_   9216     // 128x72  = 9216   (phase 3+)
#define NRM_  18432    // 128
#define PKT_  18560    // 128x136 = 17408 ; later Sc [i][j] str 132 (16896)
#define PQ_   35968    // 128x132 = 16896
#define SMW   52864
#define SMB   (SMW * 4)

// ===========================================================================
__global__ void kR() { g_flag[threadIdx.x] = 0; }

// ===========================================================================
// Persistent fused kernel: one CTA per (chunk, head), 512 threads, 1 wave.
// ===========================================================================
__global__ void __launch_bounds__(512, 1)
kP(const float* __restrict__ keys, const float* __restrict__ values,
   const float* __restrict__ queries, const float* __restrict__ feat,
   float* __restrict__ out)
{
    extern __shared__ uint32_t sm[];
    const int t = threadIdx.x, w = t >> 5, lane = t & 31;
    const int g = lane >> 2, tg = lane & 3;
    const int c = blockIdx.x, h = blockIdx.y, nbase = c * CHUNK;
    const size_t hc = (size_t)(h * NC + c);

    // ---- phase 1: stage F, K ----
    for (int idx = t; idx < MF * 16; idx += 512) {
        int m = idx >> 4, d4 = (idx & 15) << 2;
        float4 x = *(const float4*)&feat[m * DK + d4];
        sm[F_ + (d4 + 0) * STR_F + m] = f2tf(x.x);
        sm[F_ + (d4 + 1) * STR_F + m] = f2tf(x.y);
        sm[F_ + (d4 + 2) * STR_F + m] = f2tf(x.z);
        sm[F_ + (d4 + 3) * STR_F + m] = f2tf(x.w);
    }
    for (int idx = t; idx < DK * 32; idx += 512) {
        int d = idx >> 5, i4 = (idx & 31) << 2;
        float4 x = *(const float4*)&keys[(h * DK + d) * NSEQ + nbase + i4];
        sm[KQ_ + (i4 + 0) * STR_KQ + d] = f2tf(x.x);
        sm[KQ_ + (i4 + 1) * STR_KQ + d] = f2tf(x.y);
        sm[KQ_ + (i4 + 2) * STR_KQ + d] = f2tf(x.z);
        sm[KQ_ + (i4 + 3) * STR_KQ + d] = f2tf(x.w);
    }
    __syncthreads();

    const int wm0 = (w & 3) * 32, wn0 = (w >> 2) * 32;

    // ---- phase 2a: GEMM phi_k [i][m], warp tile 32x32, K=64 ----
    {
        float D[2][4][4] = {};
        for (int kk = 0; kk < 64; kk += 8) {
            uint32_t A[2][4], B[4][2];
            #pragma unroll
            for (int ms = 0; ms < 2; ms++) {
                int r0 = wm0 + ms * 16 + g;
                A[ms][0] = sm[KQ_ + r0 * STR_KQ + kk + tg];
                A[ms][1] = sm[KQ_ + (r0 + 8) * STR_KQ + kk + tg];
                A[ms][2] = sm[KQ_ + r0 * STR_KQ + kk + tg + 4];
                A[ms][3] = sm[KQ_ + (r0 + 8) * STR_KQ + kk + tg + 4];
            }
            #pragma unroll
            for (int ns = 0; ns < 4; ns++) {
                B[ns][0] = sm[F_ + (kk + tg) * STR_F + wn0 + ns * 8 + g];
                B[ns][1] = sm[F_ + (kk + tg + 4) * STR_F + wn0 + ns * 8 + g];
            }
            #pragma unroll
            for (int ms = 0; ms < 2; ms++)
                #pragma unroll
                for (int ns = 0; ns < 4; ns++) mma8(D[ms][ns], A[ms], B[ns]);
        }
        __syncthreads();   // K reads done
        // epilogue: relu*scale -> phiK^T [m][i]; restage Q over K
        #pragma unroll
        for (int ms = 0; ms < 2; ms++)
            #pragma unroll
            for (int ns = 0; ns < 4; ns++)
                #pragma unroll
                for (int e = 0; e < 4; e++) {
                    int ri = wm0 + ms * 16 + g + ((e >> 1) << 3);
                    int cm = wn0 + ns * 8 + tg * 2 + (e & 1);
                    sm[PKT_ + cm * STR_PKT + ri] =
                        f2tf(fmaxf(D[ms][ns][e], 0.f) * PHI_SCALE);
                }
        for (int idx = t; idx < DK * 32; idx += 512) {
            int d = idx >> 5, i4 = (idx & 31) << 2;
            float4 x = *(const float4*)&queries[(h * DK + d) * NSEQ + nbase + i4];
            sm[KQ_ + (i4 + 0) * STR_KQ + d] = f2tf(x.x);
            sm[KQ_ + (i4 + 1) * STR_KQ + d] = f2tf(x.y);
            sm[KQ_ + (i4 + 2) * STR_KQ + d] = f2tf(x.z);
            sm[KQ_ + (i4 + 3) * STR_KQ + d] = f2tf(x.w);
        }
    }
    __syncthreads();

    // ---- phase 2b: GEMM phi_q [i][m] ----
    {
        float D[2][4][4] = {};
        for (int kk = 0; kk < 64; kk += 8) {
            uint32_t A[2][4], B[4][2];
            #pragma unroll
            for (int ms = 0; ms < 2; ms++) {
                int r0 = wm0 + ms * 16 + g;
                A[ms][0] = sm[KQ_ + r0 * STR_KQ + kk + tg];
                A[ms][1] = sm[KQ_ + (r0 + 8) * STR_KQ + kk + tg];
                A[ms][2] = sm[KQ_ + r0 * STR_KQ + kk + tg + 4];
                A[ms][3] = sm[KQ_ + (r0 + 8) * STR_KQ + kk + tg + 4];
            }
            #pragma unroll
            for (int ns = 0; ns < 4; ns++) {
                B[ns][0] = sm[F_ + (kk + tg) * STR_F + wn0 + ns * 8 + g];
                B[ns][1] = sm[F_ + (kk + tg + 4) * STR_F + wn0 + ns * 8 + g];
            }
            #pragma unroll
            for (int ms = 0; ms < 2; ms++)
                #pragma unroll
                for (int ns = 0; ns < 4; ns++) mma8(D[ms][ns], A[ms], B[ns]);
        }
        __syncthreads();   // Q/F reads done -> R0 fully reusable
        // epilogue -> phiQ [i][m]; stage V+ over R0; zero St accumulator
        #pragma unroll
        for (int ms = 0; ms < 2; ms++)
            #pragma unroll
            for (int ns = 0; ns < 4; ns++)
                #pragma unroll
                for (int e = 0; e < 4; e++) {
                    int ri = wm0 + ms * 16 + g + ((e >> 1) << 3);
                    int cm = wn0 + ns * 8 + tg * 2 + (e & 1);
                    sm[PQ_ + ri * STR_PQ + cm] =
                        f2tf(fmaxf(D[ms][ns][e], 0.f) * PHI_SCALE);
                }
        for (int idx = t; idx < DVV * 32; idx += 512) {
            int v = idx >> 5, j4 = (idx & 31) << 2;
            float4 x = *(const float4*)&values[(h * DVV + v) * NSEQ + nbase + j4];
            sm[V_ + (j4 + 0) * STR_V + v] = f2tf(x.x);
            sm[V_ + (j4 + 1) * STR_V + v] = f2tf(x.y);
            sm[V_ + (j4 + 2) * STR_V + v] = f2tf(x.z);
            sm[V_ + (j4 + 3) * STR_V + v] = f2tf(x.w);
        }
        for (int idx = t; idx < CHUNK * 8; idx += 512) {
            int j = idx >> 3, v = 64 + (idx & 7);
            sm[V_ + j * STR_V + v] = (v == 64) ? 0x3F800000u : 0u;
        }
        for (int idx = t; idx < MF * VP / 4; idx += 512)
            ((float4*)(sm + ST_))[idx] = make_float4(0.f, 0.f, 0.f, 0.f);
    }
    __syncthreads();

    // ---- phase 3: chunk state [S|z] = phiK^T · [V;1] -> publish ----
    {
        const int m0 = (w >> 1) * 16, half = w & 1;
        const int nsB = half ? 5 : 0, nsC = half ? 4 : 5;
        float D[5][4] = {};
        for (int kk = 0; kk < CHUNK; kk += 8) {
            uint32_t A[4];
            A[0] = sm[PKT_ + (m0 + g) * STR_PKT + kk + tg];
            A[1] = sm[PKT_ + (m0 + g + 8) * STR_PKT + kk + tg];
            A[2] = sm[PKT_ + (m0 + g) * STR_PKT + kk + tg + 4];
            A[3] = sm[PKT_ + (m0 + g + 8) * STR_PKT + kk + tg + 4];
            #pragma unroll
            for (int s = 0; s < 5; s++) {
                if (s >= nsC) break;
                int ns = nsB + s;
                uint32_t B[2];
                B[0] = sm[V_ + (kk + tg) * STR_V + ns * 8 + g];
                B[1] = sm[V_ + (kk + tg + 4) * STR_V + ns * 8 + g];
                mma8(D[s], A, B);
            }
        }
        float* Sg = g_S + hc * MF * VP;
        #pragma unroll
        for (int s = 0; s < 5; s++) {
            if (s >= nsC) break;
            #pragma unroll
            for (int e = 0; e < 4; e++) {
                int row = m0 + g + ((e >> 1) << 3);
                int col = (nsB + s) * 8 + tg * 2 + (e & 1);
                Sg[row * VP + col] = D[s][e];
            }
        }
    }
    __syncthreads();
    if (t == 0) { __threadfence(); atomicExch(&g_flag[h * NC + c], 1); }

    // ---- phase 4: exclusive-prefix state St+ = sum_{c'<c} S_{c'} (in order) ----
    for (int cp = 0; cp < c; cp++) {
        if (t == 0) {
            while (atomicAdd(&g_flag[h * NC + cp], 0) == 0) {}
            __threadfence();
        }
        __syncthreads();
        const float4* src = (const float4*)(g_S + (size_t)(h * NC + cp) * MF * VP);
        float4* st = (float4*)(sm + ST_);
        for (int idx = t; idx < MF * VP / 4; idx += 512) {
            float4 a = src[idx], b = st[idx];
            b.x += a.x; b.y += a.y; b.z += a.z; b.w += a.w;
            st[idx] = b;
        }
        // same thread->idx mapping each round: no extra sync needed
    }
    // convert St to tf32 bits (same mapping -> no sync needed)
    for (int idx = t; idx < MF * VP / 4; idx += 512) {
        float4 b = ((float4*)(sm + ST_))[idx];
        uint4 u = make_uint4(f2tf(b.x), f2tf(b.y), f2tf(b.z), f2tf(b.w));
        ((uint4*)(sm + ST_))[idx] = u;
    }

    // ---- phase 5: scores = phiQ · phiK^T, warp tile 32x32, K=128 ----
    {
        float DS[2][4][4] = {};
        for (int kk = 0; kk < CHUNK; kk += 8) {
            uint32_t A[2][4], B[4][2];
            #pragma unroll
            for (int ms = 0; ms < 2; ms++) {
                int r0 = wm0 + ms * 16 + g;
                A[ms][0] = sm[PQ_ + r0 * STR_PQ + kk + tg];
                A[ms][1] = sm[PQ_ + (r0 + 8) * STR_PQ + kk + tg];
                A[ms][2] = sm[PQ_ + r0 * STR_PQ + kk + tg + 4];
                A[ms][3] = sm[PQ_ + (r0 + 8) * STR_PQ + kk + tg + 4];
            }
            #pragma unroll
            for (int ns = 0; ns < 4; ns++) {
                B[ns][0] = sm[PKT_ + (kk + tg) * STR_PKT + wn0 + ns * 8 + g];
                B[ns][1] = sm[PKT_ + (kk + tg + 4) * STR_PKT + wn0 + ns * 8 + g];
            }
            #pragma unroll
            for (int ms = 0; ms < 2; ms++)
                #pragma unroll
                for (int ns = 0; ns < 4; ns++) mma8(DS[ms][ns], A[ms], B[ns]);
        }
        __syncthreads();   // phiK^T reads done
        // mask epilogue -> Sc [i][j] over PKT region (stride 132)
        #pragma unroll
        for (int ms = 0; ms < 2; ms++)
            #pragma unroll
            for (int ns = 0; ns < 4; ns++)
                #pragma unroll
                for (int e = 0; e < 4; e++) {
                    int ri = wm0 + ms * 16 + g + ((e >> 1) << 3);
                    int cj = wn0 + ns * 8 + tg * 2 + (e & 1);
                    float s = (cj <= ri) ? DS[ms][ns][e] : 0.f;
                    sm[PKT_ + ri * STR_SC + cj] = f2tf(s);
                }
    }
    __syncthreads();

    // ---- phase 6: [out|norm] = phiQ·St+ + Sc·V+ ; 8 M-tiles x 2 N-halves ----
    {
        const int i0 = (w >> 1) * 16, half = w & 1;
        const int nsB = half ? 5 : 0, nsC = half ? 4 : 5;
        float D[5][4] = {};
        if (c > 0) {
            for (int kk = 0; kk < CHUNK; kk += 8) {      // pass 1: phiQ · St+
                uint32_t A[4];
                A[0] = sm[PQ_ + (i0 + g) * STR_PQ + kk + tg];
                A[1] = sm[PQ_ + (i0 + g + 8) * STR_PQ + kk + tg];
                A[2] = sm[PQ_ + (i0 + g) * STR_PQ + kk + tg + 4];
                A[3] = sm[PQ_ + (i0 + g + 8) * STR_PQ + kk + tg + 4];
                #pragma unroll
                for (int s = 0; s < 5; s++) {
                    if (s >= nsC) break;
                    int ns = nsB + s;
                    uint32_t B[2];
                    B[0] = sm[ST_ + (kk + tg) * STR_ST + ns * 8 + g];
                    B[1] = sm[ST_ + (kk + tg + 4) * STR_ST + ns * 8 + g];
                    mma8(D[s], A, B);
                }
            }
        }
        for (int kk = 0; kk < CHUNK; kk += 8) {          // pass 2: Sc · V+
            uint32_t A[4];
            A[0] = sm[PKT_ + (i0 + g) * STR_SC + kk + tg];
            A[1] = sm[PKT_ + (i0 + g + 8) * STR_SC + kk + tg];
            A[2] = sm[PKT_ + (i0 + g) * STR_SC + kk + tg + 4];
            A[3] = sm[PKT_ + (i0 + g + 8) * STR_SC + kk + tg + 4];
            #pragma unroll
            for (int s = 0; s < 5; s++) {
                if (s >= nsC) break;
                int ns = nsB + s;
                uint32_t B[2];
                B[0] = sm[V_ + (kk + tg) * STR_V + ns * 8 + g];
                B[1] = sm[V_ + (kk + tg + 4) * STR_V + ns * 8 + g];
                mma8(D[s], A, B);
            }
        }
        // norm = col 64 (half 1, local s=3, tg==0, e in {0,2})
        float* sNorm = (float*)(sm + NRM_);
        if (half && tg == 0) {
            sNorm[i0 + g]     = 1.0f / D[3][0];
            sNorm[i0 + g + 8] = 1.0f / D[3][2];
        }
        __syncthreads();
        const float iLo = sNorm[i0 + g], iHi = sNorm[i0 + g + 8];
        #pragma unroll
        for (int s = 0; s < 5; s++) {
            if (s >= nsC) break;
            int ns = nsB + s;
            if (ns == 8) continue;                       // cols 64..71: norm/pad
            #pragma unroll
            for (int e = 0; e < 4; e++) {
                int ri = i0 + g + ((e >> 1) << 3);
                int v  = ns * 8 + tg * 2 + (e & 1);
                out[(h * DVV + v) * NSEQ + nbase + ri] =
                    D[s][e] * ((e >> 1) ? iHi : iLo);
            }
        }
    }
}

// ===========================================================================
extern "C" void kernel_launch(void* const* d_in, const int* in_sizes, int n_in,
                              void* d_out, int out_size)
{
    const float* keys    = (const float*)d_in[0];
    const float* values  = (const float*)d_in[1];
    const float* queries = (const float*)d_in[2];
    const float* feat    = (const float*)d_in[3];
    float* out = (float*)d_out;

    cudaFuncSetAttribute(kP, cudaFuncAttributeMaxDynamicSharedMemorySize, SMB);

    kR<<<1, BH * NC>>>();
    kP<<<dim3(NC, BH), 512, SMB>>>(keys, values, queries, feat, out);
}

// round 8
// speedup vs baseline: 1.4445x; 1.4445x over previous
#include <cuda_runtime.h>
#include <cstdint>

#define BH    8
#define DK    64
#define DVV   64
#define NSEQ  2048
#define MF    128
#define CHUNK 128
#define NC    16
#define VP    72          // DV padded: col 64 = ones (z / norm), 65..71 = 0

#define PHI_SCALE 0.08838834764831845f   // 1/sqrt(128)

// Per-(head,chunk) fused chunk state [S | z | pad] : [m][VP], fp32
// (kB converts to exclusive prefix over chunks)
__device__ float g_S[BH * NC * MF * VP];     // 4.7 MB

// ---------------------------------------------------------------------------
__device__ __forceinline__ uint32_t f2tf(float f) {
    uint32_t r; asm("cvt.rna.tf32.f32 %0, %1;" : "=r"(r) : "f"(f)); return r;
}
__device__ __forceinline__ void mma8(float* d, const uint32_t* A, const uint32_t* B) {
    asm volatile("mma.sync.aligned.m16n8k8.row.col.f32.tf32.tf32.f32 "
                 "{%0,%1,%2,%3}, {%4,%5,%6,%7}, {%8,%9}, {%0,%1,%2,%3};"
                 : "+f"(d[0]), "+f"(d[1]), "+f"(d[2]), "+f"(d[3])
                 : "r"(A[0]), "r"(A[1]), "r"(A[2]), "r"(A[3]), "r"(B[0]), "r"(B[1]));
}

// Strides (words): A-operand tiles ≡4 (mod 32), B-operand tiles ≡8 (mod 32).
#define STR_KQ  68
#define STR_F   136
#define STR_PKT 136    // phiK^T [m][i]: B in scores (conflict-free), A in state GEMM
#define STR_PQ  132    // phiQ  [i][m]: A everywhere
#define STR_SC  132    // Sc    [i][j]: A
#define STR_V   72     // V+    [j][v]: B
#define STR_ST  72     // St+   [m][v]: B

// ===========================================================================
// Kernel A (512 thr): phi_k = relu(K F^T)*s ; chunk state [S|z] = phiK^T [V;1]
// ===========================================================================
#define A_F   0        // 64x136  = 8704
#define A_K   8704     // 128x68  = 8704
#define A_V   17408    // 128x72  = 9216
#define A_PKT 26624    // 128x136 = 17408
#define A_SMW 44032
#define A_SMB (A_SMW * 4)

__global__ void __launch_bounds__(512, 1)
kA(const float* __restrict__ keys, const float* __restrict__ values,
   const float* __restrict__ feat)
{
    extern __shared__ uint32_t sm[];
    const int t = threadIdx.x, w = t >> 5, lane = t & 31;
    const int g = lane >> 2, tg = lane & 3;
    const int c = blockIdx.x, h = blockIdx.y, nbase = c * CHUNK;
    const size_t hc = (size_t)(h * NC + c);

    // ---- stage F, K, V+ ----
    for (int idx = t; idx < MF * 16; idx += 512) {
        int m = idx >> 4, d4 = (idx & 15) << 2;
        float4 x = *(const float4*)&feat[m * DK + d4];
        sm[A_F + (d4 + 0) * STR_F + m] = f2tf(x.x);
        sm[A_F + (d4 + 1) * STR_F + m] = f2tf(x.y);
        sm[A_F + (d4 + 2) * STR_F + m] = f2tf(x.z);
        sm[A_F + (d4 + 3) * STR_F + m] = f2tf(x.w);
    }
    for (int idx = t; idx < DK * 32; idx += 512) {
        int d = idx >> 5, i4 = (idx & 31) << 2;
        float4 x = *(const float4*)&keys[(h * DK + d) * NSEQ + nbase + i4];
        sm[A_K + (i4 + 0) * STR_KQ + d] = f2tf(x.x);
        sm[A_K + (i4 + 1) * STR_KQ + d] = f2tf(x.y);
        sm[A_K + (i4 + 2) * STR_KQ + d] = f2tf(x.z);
        sm[A_K + (i4 + 3) * STR_KQ + d] = f2tf(x.w);
    }
    for (int idx = t; idx < DVV * 32; idx += 512) {
        int v = idx >> 5, j4 = (idx & 31) << 2;
        float4 x = *(const float4*)&values[(h * DVV + v) * NSEQ + nbase + j4];
        sm[A_V + (j4 + 0) * STR_V + v] = f2tf(x.x);
        sm[A_V + (j4 + 1) * STR_V + v] = f2tf(x.y);
        sm[A_V + (j4 + 2) * STR_V + v] = f2tf(x.z);
        sm[A_V + (j4 + 3) * STR_V + v] = f2tf(x.w);
    }
    for (int idx = t; idx < CHUNK * 8; idx += 512) {
        int j = idx >> 3, v = 64 + (idx & 7);
        sm[A_V + j * STR_V + v] = (v == 64) ? 0x3F800000u : 0u;
    }
    __syncthreads();

    const int wm0 = (w & 3) * 32, wn0 = (w >> 2) * 32;

    // ---- GEMM1: phi_k [i][m], warp tile 32x32, K=64 ----
    {
        float D[2][4][4] = {};
        #pragma unroll
        for (int kk = 0; kk < 64; kk += 8) {
            uint32_t A[2][4], B[4][2];
            #pragma unroll
            for (int ms = 0; ms < 2; ms++) {
                int r0 = wm0 + ms * 16 + g;
                A[ms][0] = sm[A_K + r0 * STR_KQ + kk + tg];
                A[ms][1] = sm[A_K + (r0 + 8) * STR_KQ + kk + tg];
                A[ms][2] = sm[A_K + r0 * STR_KQ + kk + tg + 4];
                A[ms][3] = sm[A_K + (r0 + 8) * STR_KQ + kk + tg + 4];
            }
            #pragma unroll
            for (int ns = 0; ns < 4; ns++) {
                B[ns][0] = sm[A_F + (kk + tg) * STR_F + wn0 + ns * 8 + g];
                B[ns][1] = sm[A_F + (kk + tg + 4) * STR_F + wn0 + ns * 8 + g];
            }
            #pragma unroll
            for (int ms = 0; ms < 2; ms++)
                #pragma unroll
                for (int ns = 0; ns < 4; ns++) mma8(D[ms][ns], A[ms], B[ns]);
        }
        // epilogue: relu*scale -> phiK^T [m][i]
        #pragma unroll
        for (int ms = 0; ms < 2; ms++)
            #pragma unroll
            for (int ns = 0; ns < 4; ns++)
                #pragma unroll
                for (int e = 0; e < 4; e++) {
                    int ri = wm0 + ms * 16 + g + ((e >> 1) << 3);
                    int cm = wn0 + ns * 8 + tg * 2 + (e & 1);
                    sm[A_PKT + cm * STR_PKT + ri] =
                        f2tf(fmaxf(D[ms][ns][e], 0.f) * PHI_SCALE);
                }
    }
    __syncthreads();

    // ---- GEMM2: [S|z] = phiK^T · [V;1]; 8 M-tiles x 2 N-halves ----
    {
        const int m0 = (w >> 1) * 16, half = w & 1;
        const int nsB = half ? 5 : 0, nsC = half ? 4 : 5;
        float D[5][4] = {};
        #pragma unroll
        for (int kk = 0; kk < CHUNK; kk += 8) {
            uint32_t A[4];
            A[0] = sm[A_PKT + (m0 + g) * STR_PKT + kk + tg];
            A[1] = sm[A_PKT + (m0 + g + 8) * STR_PKT + kk + tg];
            A[2] = sm[A_PKT + (m0 + g) * STR_PKT + kk + tg + 4];
            A[3] = sm[A_PKT + (m0 + g + 8) * STR_PKT + kk + tg + 4];
            #pragma unroll
            for (int s = 0; s < 5; s++) {
                if (s >= nsC) break;
                int ns = nsB + s;
                uint32_t B[2];
                B[0] = sm[A_V + (kk + tg) * STR_V + ns * 8 + g];
                B[1] = sm[A_V + (kk + tg + 4) * STR_V + ns * 8 + g];
                mma8(D[s], A, B);
            }
        }
        float* Sg = g_S + hc * MF * VP;
        #pragma unroll
        for (int s = 0; s < 5; s++) {
            if (s >= nsC) break;
            #pragma unroll
            for (int e = 0; e < 4; e++) {
                int row = m0 + g + ((e >> 1) << 3);
                int col = (nsB + s) * 8 + tg * 2 + (e & 1);
                Sg[row * VP + col] = D[s][e];
            }
        }
    }
}

// ===========================================================================
// Kernel B: exclusive prefix over chunks of g_S (elementwise)
// ===========================================================================
__global__ void __launch_bounds__(256, 1) kB()
{
    const int h = blockIdx.x, idx = blockIdx.y * 256 + threadIdx.x;  // < 9216
    float* base = g_S + (size_t)h * NC * MF * VP + idx;
    float v[NC];
    #pragma unroll
    for (int c = 0; c < NC; c++) v[c] = base[c * (MF * VP)];
    float run = 0.f;
    #pragma unroll
    for (int c = 0; c < NC; c++) { base[c * (MF * VP)] = run; run += v[c]; }
}

// ===========================================================================
// Kernel C (512 thr): recompute phi_k, phi_q; scores = mask(phiQ·phiK^T);
// [out|norm] = phiQ·St+ + Sc·V+
// ===========================================================================
#define F_    0        // 64x136 = 8704   (phase 1-2)
#define KQ_   8704     // 128x68 = 8704   (phase 1-2: K then Q)
#define V_    0        // 128x72 = 9216   (phase 3+)
#define ST_   9216     // 128x72 = 9216   (phase 3+)
#define NRM_  18432    // 128
#define PKT_  18560    // 128x136 = 17408 ; later Sc [i][j] str 132
#define PQ_   35968    // 128x132 = 16896
#define C_SMW 52864
#define C_SMB (C_SMW * 4)

__global__ void __launch_bounds__(512, 1)
kC(const float* __restrict__ keys, const float* __restrict__ values,
   const float* __restrict__ queries, const float* __restrict__ feat,
   float* __restrict__ out)
{
    extern __shared__ uint32_t sm[];
    const int t = threadIdx.x, w = t >> 5, lane = t & 31;
    const int g = lane >> 2, tg = lane & 3;
    const int c = blockIdx.x, h = blockIdx.y, nbase = c * CHUNK;
    const size_t hc = (size_t)(h * NC + c);

    // ---- phase 1: stage F, K ----
    for (int idx = t; idx < MF * 16; idx += 512) {
        int m = idx >> 4, d4 = (idx & 15) << 2;
        float4 x = *(const float4*)&feat[m * DK + d4];
        sm[F_ + (d4 + 0) * STR_F + m] = f2tf(x.x);
        sm[F_ + (d4 + 1) * STR_F + m] = f2tf(x.y);
        sm[F_ + (d4 + 2) * STR_F + m] = f2tf(x.z);
        sm[F_ + (d4 + 3) * STR_F + m] = f2tf(x.w);
    }
    for (int idx = t; idx < DK * 32; idx += 512) {
        int d = idx >> 5, i4 = (idx & 31) << 2;
        float4 x = *(const float4*)&keys[(h * DK + d) * NSEQ + nbase + i4];
        sm[KQ_ + (i4 + 0) * STR_KQ + d] = f2tf(x.x);
        sm[KQ_ + (i4 + 1) * STR_KQ + d] = f2tf(x.y);
        sm[KQ_ + (i4 + 2) * STR_KQ + d] = f2tf(x.z);
        sm[KQ_ + (i4 + 3) * STR_KQ + d] = f2tf(x.w);
    }
    __syncthreads();

    const int wm0 = (w & 3) * 32, wn0 = (w >> 2) * 32;

    // ---- phase 2a: GEMM phi_k, warp tile 32x32, K=64 ----
    {
        float D[2][4][4] = {};
        #pragma unroll
        for (int kk = 0; kk < 64; kk += 8) {
            uint32_t A[2][4], B[4][2];
            #pragma unroll
            for (int ms = 0; ms < 2; ms++) {
                int r0 = wm0 + ms * 16 + g;
                A[ms][0] = sm[KQ_ + r0 * STR_KQ + kk + tg];
                A[ms][1] = sm[KQ_ + (r0 + 8) * STR_KQ + kk + tg];
                A[ms][2] = sm[KQ_ + r0 * STR_KQ + kk + tg + 4];
                A[ms][3] = sm[KQ_ + (r0 + 8) * STR_KQ + kk + tg + 4];
            }
            #pragma unroll
            for (int ns = 0; ns < 4; ns++) {
                B[ns][0] = sm[F_ + (kk + tg) * STR_F + wn0 + ns * 8 + g];
                B[ns][1] = sm[F_ + (kk + tg + 4) * STR_F + wn0 + ns * 8 + g];
            }
            #pragma unroll
            for (int ms = 0; ms < 2; ms++)
                #pragma unroll
                for (int ns = 0; ns < 4; ns++) mma8(D[ms][ns], A[ms], B[ns]);
        }
        __syncthreads();   // K reads done
        // epilogue -> phiK^T [m][i]; restage Q over K
        #pragma unroll
        for (int ms = 0; ms < 2; ms++)
            #pragma unroll
            for (int ns = 0; ns < 4; ns++)
                #pragma unroll
                for (int e = 0; e < 4; e++) {
                    int ri = wm0 + ms * 16 + g + ((e >> 1) << 3);
                    int cm = wn0 + ns * 8 + tg * 2 + (e & 1);
                    sm[PKT_ + cm * STR_PKT + ri] =
                        f2tf(fmaxf(D[ms][ns][e], 0.f) * PHI_SCALE);
                }
        for (int idx = t; idx < DK * 32; idx += 512) {
            int d = idx >> 5, i4 = (idx & 31) << 2;
            float4 x = *(const float4*)&queries[(h * DK + d) * NSEQ + nbase + i4];
            sm[KQ_ + (i4 + 0) * STR_KQ + d] = f2tf(x.x);
            sm[KQ_ + (i4 + 1) * STR_KQ + d] = f2tf(x.y);
            sm[KQ_ + (i4 + 2) * STR_KQ + d] = f2tf(x.z);
            sm[KQ_ + (i4 + 3) * STR_KQ + d] = f2tf(x.w);
        }
    }
    __syncthreads();

    // ---- phase 2b: GEMM phi_q [i][m] ----
    {
        float D[2][4][4] = {};
        #pragma unroll
        for (int kk = 0; kk < 64; kk += 8) {
            uint32_t A[2][4], B[4][2];
            #pragma unroll
            for (int ms = 0; ms < 2; ms++) {
                int r0 = wm0 + ms * 16 + g;
                A[ms][0] = sm[KQ_ + r0 * STR_KQ + kk + tg];
                A[ms][1] = sm[KQ_ + (r0 + 8) * STR_KQ + kk + tg];
                A[ms][2] = sm[KQ_ + r0 * STR_KQ + kk + tg + 4];
                A[ms][3] = sm[KQ_ + (r0 + 8) * STR_KQ + kk + tg + 4];
            }
            #pragma unroll
            for (int ns = 0; ns < 4; ns++) {
                B[ns][0] = sm[F_ + (kk + tg) * STR_F + wn0 + ns * 8 + g];
                B[ns][1] = sm[F_ + (kk + tg + 4) * STR_F + wn0 + ns * 8 + g];
            }
            #pragma unroll
            for (int ms = 0; ms < 2; ms++)
                #pragma unroll
                for (int ns = 0; ns < 4; ns++) mma8(D[ms][ns], A[ms], B[ns]);
        }
        __syncthreads();   // Q/F reads done -> region 0 reusable
        // epilogue -> phiQ [i][m]; stage V+, St+ over region 0
        #pragma unroll
        for (int ms = 0; ms < 2; ms++)
            #pragma unroll
            for (int ns = 0; ns < 4; ns++)
                #pragma unroll
                for (int e = 0; e < 4; e++) {
                    int ri = wm0 + ms * 16 + g + ((e >> 1) << 3);
                    int cm = wn0 + ns * 8 + tg * 2 + (e & 1);
                    sm[PQ_ + ri * STR_PQ + cm] =
                        f2tf(fmaxf(D[ms][ns][e], 0.f) * PHI_SCALE);
                }
        for (int idx = t; idx < DVV * 32; idx += 512) {
            int v = idx >> 5, j4 = (idx & 31) << 2;
            float4 x = *(const float4*)&values[(h * DVV + v) * NSEQ + nbase + j4];
            sm[V_ + (j4 + 0) * STR_V + v] = f2tf(x.x);
            sm[V_ + (j4 + 1) * STR_V + v] = f2tf(x.y);
            sm[V_ + (j4 + 2) * STR_V + v] = f2tf(x.z);
            sm[V_ + (j4 + 3) * STR_V + v] = f2tf(x.w);
        }
        for (int idx = t; idx < CHUNK * 8; idx += 512) {
            int j = idx >> 3, v = 64 + (idx & 7);
            sm[V_ + j * STR_V + v] = (v == 64) ? 0x3F800000u : 0u;
        }
        {
            const float4* Sg = (const float4*)(g_S + hc * MF * VP);
            for (int idx = t; idx < MF * VP / 4; idx += 512) {
                float4 x = Sg[idx];
                ((uint4*)(sm + ST_))[idx] =
                    make_uint4(f2tf(x.x), f2tf(x.y), f2tf(x.z), f2tf(x.w));
            }
        }
    }
    __syncthreads();

    // ---- phase 3: scores = phiQ · phiK^T, warp tile 32x32, K=128 ----
    {
        float DS[2][4][4] = {};
        #pragma unroll
        for (int kk = 0; kk < CHUNK; kk += 8) {
            uint32_t A[2][4], B[4][2];
            #pragma unroll
            for (int ms = 0; ms < 2; ms++) {
                int r0 = wm0 + ms * 16 + g;
                A[ms][0] = sm[PQ_ + r0 * STR_PQ + kk + tg];
                A[ms][1] = sm[PQ_ + (r0 + 8) * STR_PQ + kk + tg];
                A[ms][2] = sm[PQ_ + r0 * STR_PQ + kk + tg + 4];
                A[ms][3] = sm[PQ_ + (r0 + 8) * STR_PQ + kk + tg + 4];
            }
            #pragma unroll
            for (int ns = 0; ns < 4; ns++) {
                B[ns][0] = sm[PKT_ + (kk + tg) * STR_PKT + wn0 + ns * 8 + g];
                B[ns][1] = sm[PKT_ + (kk + tg + 4) * STR_PKT + wn0 + ns * 8 + g];
            }
            #pragma unroll
            for (int ms = 0; ms < 2; ms++)
                #pragma unroll
                for (int ns = 0; ns < 4; ns++) mma8(DS[ms][ns], A[ms], B[ns]);
        }
        __syncthreads();   // phiK^T reads done
        // mask epilogue -> Sc [i][j] (overwrites PKT region, stride 132)
        #pragma unroll
        for (int ms = 0; ms < 2; ms++)
            #pragma unroll
            for (int ns = 0; ns < 4; ns++)
                #pragma unroll
                for (int e = 0; e < 4; e++) {
                    int ri = wm0 + ms * 16 + g + ((e >> 1) << 3);
                    int cj = wn0 + ns * 8 + tg * 2 + (e & 1);
                    float s = (cj <= ri) ? DS[ms][ns][e] : 0.f;
                    sm[PKT_ + ri * STR_SC + cj] = f2tf(s);
                }
    }
    __syncthreads();

    // ---- phase 4: [out|norm] = phiQ·St+ + Sc·V+ ; 8 M-tiles x 2 N-halves ----
    {
        const int i0 = (w >> 1) * 16, half = w & 1;
        const int nsB = half ? 5 : 0, nsC = half ? 4 : 5;
        float D[5][4] = {};
        if (c > 0) {
            #pragma unroll
            for (int kk = 0; kk < CHUNK; kk += 8) {      // pass 1: phiQ · St+
                uint32_t A[4];
                A[0] = sm[PQ_ + (i0 + g) * STR_PQ + kk + tg];
                A[1] = sm[PQ_ + (i0 + g + 8) * STR_PQ + kk + tg];
                A[2] = sm[PQ_ + (i0 + g) * STR_PQ + kk + tg + 4];
                A[3] = sm[PQ_ + (i0 + g + 8) * STR_PQ + kk + tg + 4];
                #pragma unroll
                for (int s = 0; s < 5; s++) {
                    if (s >= nsC) break;
                    int ns = nsB + s;
                    uint32_t B[2];
                    B[0] = sm[ST_ + (kk + tg) * STR_ST + ns * 8 + g];
                    B[1] = sm[ST_ + (kk + tg + 4) * STR_ST + ns * 8 + g];
                    mma8(D[s], A, B);
                }
            }
        }
        #pragma unroll
        for (int kk = 0; kk < CHUNK; kk += 8) {          // pass 2: Sc · V+
            uint32_t A[4];
            A[0] = sm[PKT_ + (i0 + g) * STR_SC + kk + tg];
            A[1] = sm[PKT_ + (i0 + g + 8) * STR_SC + kk + tg];
            A[2] = sm[PKT_ + (i0 + g) * STR_SC + kk + tg + 4];
            A[3] = sm[PKT_ + (i0 + g + 8) * STR_SC + kk + tg + 4];
            #pragma unroll
            for (int s = 0; s < 5; s++) {
                if (s >= nsC) break;
                int ns = nsB + s;
                uint32_t B[2];
                B[0] = sm[V_ + (kk + tg) * STR_V + ns * 8 + g];
                B[1] = sm[V_ + (kk + tg + 4) * STR_V + ns * 8 + g];
                mma8(D[s], A, B);
            }
        }
        // norm = col 64 (half 1, local s=3, tg==0, e in {0,2})
        float* sNorm = (float*)(sm + NRM_);
        if (half && tg == 0) {
            sNorm[i0 + g]     = 1.0f / D[3][0];
            sNorm[i0 + g + 8] = 1.0f / D[3][2];
        }
        __syncthreads();
        const float iLo = sNorm[i0 + g], iHi = sNorm[i0 + g + 8];
        #pragma unroll
        for (int s = 0; s < 5; s++) {
            if (s >= nsC) break;
            int ns = nsB + s;
            if (ns == 8) continue;                       // cols 64..71: norm/pad
            #pragma unroll
            for (int e = 0; e < 4; e++) {
                int ri = i0 + g + ((e >> 1) << 3);
                int v  = ns * 8 + tg * 2 + (e & 1);
                out[(h * DVV + v) * NSEQ + nbase + ri] =
                    D[s][e] * ((e >> 1) ? iHi : iLo);
            }
        }
    }
}

// ===========================================================================
extern "C" void kernel_launch(void* const* d_in, const int* in_sizes, int n_in,
                              void* d_out, int out_size)
{
    const float* keys    = (const float*)d_in[0];
    const float* values  = (const float*)d_in[1];
    const float* queries = (const float*)d_in[2];
    const float* feat    = (const float*)d_in[3];
    float* out = (float*)d_out;

    cudaFuncSetAttribute(kA, cudaFuncAttributeMaxDynamicSharedMemorySize, A_SMB);
    cudaFuncSetAttribute(kC, cudaFuncAttributeMaxDynamicSharedMemorySize, C_SMB);

    kA<<<dim3(NC, BH), 512, A_SMB>>>(keys, values, feat);
    kB<<<dim3(BH, 36), 256>>>();
    kC<<<dim3(NC, BH), 512, C_SMB>>>(keys, values, queries, feat, out);
}